// round 13
// baseline (speedup 1.0000x reference)
#include <cuda_runtime.h>
#include <cuda_fp16.h>
#include <cstdint>
#include <math.h>

#define B_  4
#define T_  2048
#define D_  1024
#define H_  16
#define BT_ (B_ * T_)
#define LOG2E 1.4426950408889634f

typedef unsigned long long u64;

// GEMM inputs: x fp16, W fp16
__device__ __half g_xf[(size_t)BT_ * D_];
__device__ __half g_wf[3ull * D_ * D_];
// Attention operands: fp16
__device__ __half g_qf[(size_t)BT_ * D_];
__device__ __half g_kf[(size_t)BT_ * D_];
__device__ __half g_vf[(size_t)BT_ * D_];

// ---- portable PTX helpers -------------------------------------------------
__device__ __forceinline__ uint32_t smem_u32(const void* p) {
    uint32_t a;
    asm("{ .reg .u64 t; cvta.to.shared.u64 t, %1; cvt.u32.u64 %0, t; }"
        : "=r"(a) : "l"(p));
    return a;
}
__device__ __forceinline__ void cp16(uint32_t s, const void* g) {
    asm volatile("cp.async.cg.shared.global [%0], [%1], 16;"
                 :: "r"(s), "l"(g) : "memory");
}
#define CP_COMMIT() asm volatile("cp.async.commit_group;" ::: "memory")
#define CP_WAIT(n)  asm volatile("cp.async.wait_group %0;" :: "n"(n) : "memory")

__device__ __forceinline__ void mma_f16(float& d0, float& d1, float& d2, float& d3,
                                        uint32_t a0, uint32_t a1, uint32_t a2, uint32_t a3,
                                        uint32_t b0, uint32_t b1) {
    asm volatile("mma.sync.aligned.m16n8k16.row.col.f32.f16.f16.f32 "
                 "{%0,%1,%2,%3},{%4,%5,%6,%7},{%8,%9},{%0,%1,%2,%3};"
                 : "+f"(d0), "+f"(d1), "+f"(d2), "+f"(d3)
                 : "r"(a0), "r"(a1), "r"(a2), "r"(a3), "r"(b0), "r"(b1));
}
__device__ __forceinline__ void ldsm4t(uint32_t& r0, uint32_t& r1,
                                       uint32_t& r2, uint32_t& r3, uint32_t a) {
    asm volatile("ldmatrix.sync.aligned.m8n8.x4.trans.shared.b16 {%0,%1,%2,%3}, [%4];"
                 : "=r"(r0), "=r"(r1), "=r"(r2), "=r"(r3) : "r"(a));
}
// ---- packed f32x2 ---------------------------------------------------------
__device__ __forceinline__ u64 pk2(float lo, float hi) {
    u64 r; asm("mov.b64 %0,{%1,%2};" : "=l"(r) : "f"(lo), "f"(hi)); return r;
}
__device__ __forceinline__ void upk2(u64 v, float& lo, float& hi) {
    asm("mov.b64 {%0,%1},%2;" : "=f"(lo), "=f"(hi) : "l"(v));
}
__device__ __forceinline__ u64 fma2(u64 a, u64 b, u64 c) {
    u64 d; asm("fma.rn.f32x2 %0,%1,%2,%3;" : "=l"(d) : "l"(a), "l"(b), "l"(c)); return d;
}
__device__ __forceinline__ u64 mul2(u64 a, u64 b) {
    u64 d; asm("mul.rn.f32x2 %0,%1,%2;" : "=l"(d) : "l"(a), "l"(b)); return d;
}
__device__ __forceinline__ u64 add2(u64 a, u64 b) {
    u64 d; asm("add.rn.f32x2 %0,%1,%2;" : "=l"(d) : "l"(a), "l"(b)); return d;
}

// ===========================================================================
// Kernel 0a: x -> fp16
// ===========================================================================
__global__ __launch_bounds__(256) void convert_x(
    const float* __restrict__ src, __half* __restrict__ dst, int n4)
{
    int i = blockIdx.x * blockDim.x + threadIdx.x;
    if (i >= n4) return;
    float4 v = ((const float4*)src)[i];
    uint2 hp;
    unsigned short* hu = (unsigned short*)&hp;
    hu[0] = __half_as_ushort(__float2half_rn(v.x));
    hu[1] = __half_as_ushort(__float2half_rn(v.y));
    hu[2] = __half_as_ushort(__float2half_rn(v.z));
    hu[3] = __half_as_ushort(__float2half_rn(v.w));
    ((uint2*)dst)[i] = hp;
}

// Kernel 0b: W -> fp16, three mats in one launch
__global__ __launch_bounds__(256) void convert_w(
    const float* __restrict__ wq, const float* __restrict__ wk,
    const float* __restrict__ wv, int n4)
{
    int i = blockIdx.x * blockDim.x + threadIdx.x;
    if (i >= n4) return;
    const float* src = (blockIdx.y == 0) ? wq : ((blockIdx.y == 1) ? wk : wv);
    size_t off = (size_t)blockIdx.y * D_ * D_ / 4;
    float4 v = ((const float4*)src)[i];
    uint2 hp;
    unsigned short* hu = (unsigned short*)&hp;
    hu[0] = __half_as_ushort(__float2half_rn(v.x));
    hu[1] = __half_as_ushort(__float2half_rn(v.y));
    hu[2] = __half_as_ushort(__float2half_rn(v.z));
    hu[3] = __half_as_ushort(__float2half_rn(v.w));
    ((uint2*)(g_wf))[off + i] = hp;
}

// ===========================================================================
// Kernel 1: QKV projection, single fp16 mma.sync (unchanged from R11)
// ===========================================================================
#define TILE_E   (128 * 40)
#define TILE_B   (TILE_E * 2)
#define GEMM_SMEM (2 * 2 * TILE_B)

__global__ __launch_bounds__(256, 2) void qkv_gemm_mma()
{
    extern __shared__ __align__(16) char smem[];
    __half* sb = (__half*)smem;
    const uint32_t sbase = smem_u32(smem);

    const int tid  = threadIdx.x;
    const int lane = tid & 31;
    const int wid  = tid >> 5;
    const int wm   = (wid >> 1) * 32;
    const int wn   = (wid & 1) * 64;
    const int n0   = blockIdx.x * 128;
    const int m0   = blockIdx.y * 128;
    const int mat  = blockIdx.z;

    const __half* A_g = g_xf + (size_t)m0 * D_;
    const __half* B_g = g_wf + (size_t)mat * D_ * D_ + (size_t)n0 * D_;
    __half* yf = (mat == 0) ? g_qf : ((mat == 1) ? g_kf : g_vf);

    const int lrow  = tid >> 1;
    const int lhalf = tid & 1;

    float acc[2][8][4];
#pragma unroll
    for (int i = 0; i < 2; i++)
#pragma unroll
        for (int j = 0; j < 8; j++)
#pragma unroll
            for (int c = 0; c < 4; c++) acc[i][j][c] = 0.0f;

    const int r  = lane >> 2;
    const int c2 = (lane & 3) * 2;

    auto load_tiles = [&](int buf, int k0) {
        const size_t go = (size_t)lrow * D_ + k0 + lhalf * 16;
        const uint32_t so = sbase + buf * 2 * TILE_B + lrow * 80 + lhalf * 32;
        cp16(so + 0 * TILE_B,      A_g + go);
        cp16(so + 0 * TILE_B + 16, A_g + go + 8);
        cp16(so + 1 * TILE_B,      B_g + go);
        cp16(so + 1 * TILE_B + 16, B_g + go + 8);
    };

    load_tiles(0, 0);
    CP_COMMIT();

    for (int it = 0; it < 32; it++) {
        const int cur = it & 1;
        if (it + 1 < 32) {
            load_tiles(cur ^ 1, (it + 1) * 32);
            CP_COMMIT();
            CP_WAIT(1);
        } else {
            CP_WAIT(0);
        }
        __syncthreads();

        const __half* Ah = sb + (cur * 2 + 0) * TILE_E;
        const __half* Bh = sb + (cur * 2 + 1) * TILE_E;

#pragma unroll
        for (int ks = 0; ks < 2; ks++) {
            const int kof = ks * 16;
            uint32_t ah[2][4];
#pragma unroll
            for (int mm = 0; mm < 2; mm++) {
                int row0 = wm + mm * 16 + r;
                const __half* p = Ah + row0 * 40 + kof + c2;
                ah[mm][0] = *(const uint32_t*)(p);
                ah[mm][1] = *(const uint32_t*)(p + 8 * 40);
                ah[mm][2] = *(const uint32_t*)(p + 8);
                ah[mm][3] = *(const uint32_t*)(p + 8 * 40 + 8);
            }
#pragma unroll
            for (int nn = 0; nn < 8; nn++) {
                int nrow = wn + nn * 8 + r;
                const __half* pb = Bh + nrow * 40 + kof + c2;
                uint32_t b0 = *(const uint32_t*)(pb);
                uint32_t b1 = *(const uint32_t*)(pb + 8);
#pragma unroll
                for (int mm = 0; mm < 2; mm++) {
                    float* d = acc[mm][nn];
                    mma_f16(d[0], d[1], d[2], d[3],
                            ah[mm][0], ah[mm][1], ah[mm][2], ah[mm][3], b0, b1);
                }
            }
        }
        __syncthreads();
    }

#pragma unroll
    for (int mm = 0; mm < 2; mm++) {
#pragma unroll
        for (int nn = 0; nn < 8; nn++) {
            int row = m0 + wm + mm * 16 + r;
            int col = n0 + wn + nn * 8 + c2;
            __half2 h01 = __floats2half2_rn(acc[mm][nn][0], acc[mm][nn][1]);
            *(uint32_t*)&yf[(size_t)row * D_ + col] = *(uint32_t*)&h01;
            __half2 h23 = __floats2half2_rn(acc[mm][nn][2], acc[mm][nn][3]);
            *(uint32_t*)&yf[(size_t)(row + 8) * D_ + col] = *(uint32_t*)&h23;
        }
    }
}

// ===========================================================================
// Kernel 2: palace attention — R11 structure (256 thr, 4m x 2n warps,
// 32x64 warp tiles, 1 CTA/SM). Change vs R11: row-sum moved OFF the tensor
// pipe (f32 adds during exp + one quad shfl pair) — frees ~6% of MMA issues.
// ===========================================================================
#define TB    18432
#define ROWB  144
#define ATTN_SMEM (5 * TB)

__global__ __launch_bounds__(256, 1) void palace_attn_tc(
    const float* __restrict__ wp, float* __restrict__ out)
{
    extern __shared__ __align__(128) char smem[];
    const uint32_t sb32 = smem_u32(smem);
    const int tid  = threadIdx.x;
    const int lane = tid & 31;
    const int wid  = tid >> 5;
    const int wm4  = wid >> 1;
    const int wn2  = wid & 1;
    const int r_   = lane >> 2;
    const int cq   = lane & 3;
    const int qt   = blockIdx.x;
    const int bh   = blockIdx.y;
    const int b    = bh >> 4;
    const int h    = bh & 15;

    const float sigw = 1.0f / (1.0f + expf(-wp[0]));
    const float cI = 0.125f * LOG2E;
    const float cX = cI * sigw;
    const u64 cI2 = pk2(cI, cI), cX2 = pk2(cX, cX);
    const u64 magic2  = pk2(12582912.0f, 12582912.0f);
    const u64 nmagic2 = pk2(-12582912.0f, -12582912.0f);
    const u64 neg1_2  = pk2(-1.0f, -1.0f);
    const u64 T4 = pk2(9.6181291e-3f, 9.6181291e-3f);
    const u64 T3 = pk2(5.5504109e-2f, 5.5504109e-2f);
    const u64 T2 = pk2(2.4022651e-1f, 2.4022651e-1f);
    const u64 T1 = pk2(6.9314718e-1f, 6.9314718e-1f);
    const u64 T0 = pk2(1.0f, 1.0f);

    const int lrow  = tid >> 1;
    const int lhalf = tid & 1;
    const size_t grow_base = ((size_t)b * T_) * D_ + (size_t)h * 64 + lhalf * 32;

    auto ld4 = [&](uint32_t soff, const __half* gp) {
#pragma unroll
        for (int kk = 0; kk < 4; kk++)
            cp16(sb32 + soff + lrow * ROWB + lhalf * 64 + kk * 16, gp + kk * 8);
    };
    {
        const size_t go = grow_base + (size_t)(qt * 128 + lrow) * D_;
        ld4(0, g_qf + go);
    }
    auto ldkv = [&](int buf, int kt) {
        const size_t go = grow_base + (size_t)(kt * 128 + lrow) * D_;
        const uint32_t off = TB + buf * 2 * TB;
        ld4(off,      g_kf + go);
        ld4(off + TB, g_vf + go);
    };
    ldkv(0, 0);
    CP_COMMIT();

    float o[2][8][4];
    float lsf[2][2] = {{0.f, 0.f}, {0.f, 0.f}};   // row-sums: [mm][half]
#pragma unroll
    for (int mm = 0; mm < 2; mm++)
#pragma unroll
        for (int j = 0; j < 8; j++)
#pragma unroll
            for (int c = 0; c < 4; c++) o[mm][j][c] = 0.f;

    const int arowb = wm4 * 32 + r_;
    const int krowb = wn2 * 64 + r_;
    const int vg = lane >> 3, vrr = lane & 7;
    const int vrow_off = wn2 * 64 + ((vg & 1) ? 8 : 0) + vrr;
    const int vcolB = ((vg >> 1) * 8) * 2;
    const int blk0base = (wm4 & 1) * 4;

    for (int kt = 0; kt < 16; kt++) {
        const int cur = kt & 1;
        if (kt + 1 < 16) { ldkv(cur ^ 1, kt + 1); CP_COMMIT(); CP_WAIT(1); }
        else             { CP_WAIT(0); }
        __syncthreads();

        const uint32_t KHo = TB + cur * 2 * TB;
        const uint32_t VHo = KHo + TB;

        // ---- S = Q K^T ----
        float s[2][8][4];
#pragma unroll
        for (int mm = 0; mm < 2; mm++)
#pragma unroll
            for (int j = 0; j < 8; j++)
#pragma unroll
                for (int c = 0; c < 4; c++) s[mm][j][c] = 0.f;

#pragma unroll
        for (int ks = 0; ks < 4; ks++) {
            const int cb = (ks * 16 + 2 * cq) * 2;
            uint32_t aq[2][4];
#pragma unroll
            for (int mm = 0; mm < 2; mm++) {
                const char* q0 = smem + (arowb + mm * 16) * ROWB + cb;
                aq[mm][0] = *(const uint32_t*)(q0);
                aq[mm][1] = *(const uint32_t*)(q0 + 8 * ROWB);
                aq[mm][2] = *(const uint32_t*)(q0 + 16);
                aq[mm][3] = *(const uint32_t*)(q0 + 8 * ROWB + 16);
            }
#pragma unroll
            for (int j = 0; j < 8; j++) {
                const char* kp = smem + KHo + (krowb + j * 8) * ROWB + cb;
                uint32_t b0 = *(const uint32_t*)(kp);
                uint32_t b1 = *(const uint32_t*)(kp + 16);
#pragma unroll
                for (int mm = 0; mm < 2; mm++) {
                    float* d = s[mm][j];
                    mma_f16(d[0], d[1], d[2], d[3],
                            aq[mm][0], aq[mm][1], aq[mm][2], aq[mm][3], b0, b1);
                }
            }
        }

        // ---- exp2 softmax (deg-4 packed, IADD exponent) + f32 lsum + PV ----
#pragma unroll
        for (int t = 0; t < 4; t++) {
            uint32_t ph[2][4];
#pragma unroll
            for (int jj = 0; jj < 2; jj++) {
                const int j = 2 * t + jj;
#pragma unroll
                for (int mm = 0; mm < 2; mm++) {
                    const int blk0 = blk0base + mm * 2;
#pragma unroll
                    for (int half = 0; half < 2; half++) {
                        const u64 mf2 = (j == blk0 + half) ? cI2 : cX2;
                        u64 s2 = pk2(s[mm][j][half * 2], s[mm][j][half * 2 + 1]);
                        u64 x2 = mul2(s2, mf2);
                        u64 t2 = add2(x2, magic2);
                        u64 n2 = add2(t2, nmagic2);
                        u64 f2 = fma2(n2, neg1_2, x2);
                        u64 p2 = fma2(T4, f2, T3);
                        p2 = fma2(p2, f2, T2);
                        p2 = fma2(p2, f2, T1);
                        p2 = fma2(p2, f2, T0);
                        uint32_t tl = (uint32_t)t2, th = (uint32_t)(t2 >> 32);
                        float p0, p1; upk2(p2, p0, p1);
                        float pe0 = __uint_as_float(__float_as_uint(p0) + (tl << 23));
                        float pe1 = __uint_as_float(__float_as_uint(p1) + (th << 23));
                        lsf[mm][half] += pe0 + pe1;
                        __half2 h2 = __floats2half2_rn(pe0, pe1);
                        ph[mm][jj * 2 + half] = *(uint32_t*)&h2;
                    }
                }
            }
            const uint32_t va0 = sb32 + VHo + (vrow_off + t * 16) * ROWB + vcolB;
#pragma unroll
            for (int jnp = 0; jnp < 4; jnp++) {
                uint32_t v0, v1, v2, v3;
                ldsm4t(v0, v1, v2, v3, va0 + jnp * 32);
#pragma unroll
                for (int mm = 0; mm < 2; mm++) {
                    float* o0 = o[mm][jnp * 2];
                    mma_f16(o0[0], o0[1], o0[2], o0[3],
                            ph[mm][0], ph[mm][1], ph[mm][2], ph[mm][3], v0, v1);
                    float* o1 = o[mm][jnp * 2 + 1];
                    mma_f16(o1[0], o1[1], o1[2], o1[3],
                            ph[mm][0], ph[mm][1], ph[mm][2], ph[mm][3], v2, v3);
                }
            }
        }
        __syncthreads();
    }

    // ---- quad reduction of row-sums (across cq lanes) ----
#pragma unroll
    for (int mm = 0; mm < 2; mm++)
#pragma unroll
        for (int half = 0; half < 2; half++) {
            float v = lsf[mm][half];
            v += __shfl_xor_sync(0xffffffffu, v, 1);
            v += __shfl_xor_sync(0xffffffffu, v, 2);
            lsf[mm][half] = v;
        }

    // ---- cross-warp combine (wn2 pair shares rows) ----
    float* Ost = (float*)(smem + TB);
    float* Lst = (float*)(smem + TB + 128 * 68 * 4);
    if (wn2 == 1) {
#pragma unroll
        for (int mm = 0; mm < 2; mm++) {
            int row = wm4 * 32 + mm * 16 + r_;
#pragma unroll
            for (int jn = 0; jn < 8; jn++) {
                int col = jn * 8 + 2 * cq;
                *(float2*)&Ost[row * 68 + col]       = make_float2(o[mm][jn][0], o[mm][jn][1]);
                *(float2*)&Ost[(row + 8) * 68 + col] = make_float2(o[mm][jn][2], o[mm][jn][3]);
            }
            if (cq == 0) {
                Lst[row]     = lsf[mm][0];
                Lst[row + 8] = lsf[mm][1];
            }
        }
    }
    __syncthreads();
    if (wn2 == 0) {
#pragma unroll
        for (int mm = 0; mm < 2; mm++) {
            int row = wm4 * 32 + mm * 16 + r_;
            float inv0 = 1.0f / (lsf[mm][0] + Lst[row]);
            float inv1 = 1.0f / (lsf[mm][1] + Lst[row + 8]);
            float* op0 = out + ((size_t)b * T_ + qt * 128 + row) * D_ + h * 64;
            float* op1 = op0 + 8 * D_;
#pragma unroll
            for (int jn = 0; jn < 8; jn++) {
                int col = jn * 8 + 2 * cq;
                float2 a0 = *(float2*)&Ost[row * 68 + col];
                float2 a1 = *(float2*)&Ost[(row + 8) * 68 + col];
                float2 w0 = make_float2((o[mm][jn][0] + a0.x) * inv0,
                                        (o[mm][jn][1] + a0.y) * inv0);
                float2 w1 = make_float2((o[mm][jn][2] + a1.x) * inv1,
                                        (o[mm][jn][3] + a1.y) * inv1);
                *(float2*)&op0[col] = w0;
                *(float2*)&op1[col] = w1;
            }
        }
    }
}

// ---------------------------------------------------------------------------
extern "C" void kernel_launch(void* const* d_in, const int* in_sizes, int n_in,
                              void* d_out, int out_size)
{
    const float* x  = (const float*)d_in[0];
    const float* Wq = (const float*)d_in[1];
    const float* Wk = (const float*)d_in[2];
    const float* Wv = (const float*)d_in[3];
    const float* wp = (const float*)d_in[4];
    float* out = (float*)d_out;

    __half* xf;
    cudaGetSymbolAddress((void**)&xf, g_xf);

    cudaFuncSetAttribute(qkv_gemm_mma, cudaFuncAttributeMaxDynamicSharedMemorySize,
                         GEMM_SMEM);
    cudaFuncSetAttribute(palace_attn_tc, cudaFuncAttributeMaxDynamicSharedMemorySize,
                         ATTN_SMEM);

    int n4x = BT_ * D_ / 4;
    convert_x<<<(n4x + 255) / 256, 256>>>(x, xf, n4x);
    int n4w = D_ * D_ / 4;
    convert_w<<<dim3((n4w + 255) / 256, 3), 256>>>(Wq, Wk, Wv, n4w);

    qkv_gemm_mma<<<dim3(8, 64, 3), 256, GEMM_SMEM>>>();
    palace_attn_tc<<<dim3(T_ / 128, B_ * H_), 256, ATTN_SMEM>>>(wp, out);
}

// round 15
// speedup vs baseline: 1.0038x; 1.0038x over previous
#include <cuda_runtime.h>
#include <cuda_fp16.h>
#include <cstdint>
#include <math.h>

#define B_  4
#define T_  2048
#define D_  1024
#define H_  16
#define BT_ (B_ * T_)
#define LOG2E 1.4426950408889634f

typedef unsigned long long u64;

// GEMM inputs: x fp16, W fp16
__device__ __half g_xf[(size_t)BT_ * D_];
__device__ __half g_wf[3ull * D_ * D_];
// Attention operands: fp16
__device__ __half g_qf[(size_t)BT_ * D_];
__device__ __half g_kf[(size_t)BT_ * D_];
__device__ __half g_vf[(size_t)BT_ * D_];

// ---- portable PTX helpers -------------------------------------------------
__device__ __forceinline__ uint32_t smem_u32(const void* p) {
    uint32_t a;
    asm("{ .reg .u64 t; cvta.to.shared.u64 t, %1; cvt.u32.u64 %0, t; }"
        : "=r"(a) : "l"(p));
    return a;
}
__device__ __forceinline__ void cp16(uint32_t s, const void* g) {
    asm volatile("cp.async.cg.shared.global [%0], [%1], 16;"
                 :: "r"(s), "l"(g) : "memory");
}
#define CP_COMMIT() asm volatile("cp.async.commit_group;" ::: "memory")
#define CP_WAIT(n)  asm volatile("cp.async.wait_group %0;" :: "n"(n) : "memory")

__device__ __forceinline__ void mma_f16(float& d0, float& d1, float& d2, float& d3,
                                        uint32_t a0, uint32_t a1, uint32_t a2, uint32_t a3,
                                        uint32_t b0, uint32_t b1) {
    asm volatile("mma.sync.aligned.m16n8k16.row.col.f32.f16.f16.f32 "
                 "{%0,%1,%2,%3},{%4,%5,%6,%7},{%8,%9},{%0,%1,%2,%3};"
                 : "+f"(d0), "+f"(d1), "+f"(d2), "+f"(d3)
                 : "r"(a0), "r"(a1), "r"(a2), "r"(a3), "r"(b0), "r"(b1));
}
__device__ __forceinline__ void ldsm4t(uint32_t& r0, uint32_t& r1,
                                       uint32_t& r2, uint32_t& r3, uint32_t a) {
    asm volatile("ldmatrix.sync.aligned.m8n8.x4.trans.shared.b16 {%0,%1,%2,%3}, [%4];"
                 : "=r"(r0), "=r"(r1), "=r"(r2), "=r"(r3) : "r"(a));
}
// ---- packed f32x2 ---------------------------------------------------------
__device__ __forceinline__ u64 pk2(float lo, float hi) {
    u64 r; asm("mov.b64 %0,{%1,%2};" : "=l"(r) : "f"(lo), "f"(hi)); return r;
}
__device__ __forceinline__ void upk2(u64 v, float& lo, float& hi) {
    asm("mov.b64 {%0,%1},%2;" : "=f"(lo), "=f"(hi) : "l"(v));
}
__device__ __forceinline__ u64 fma2(u64 a, u64 b, u64 c) {
    u64 d; asm("fma.rn.f32x2 %0,%1,%2,%3;" : "=l"(d) : "l"(a), "l"(b), "l"(c)); return d;
}
__device__ __forceinline__ u64 mul2(u64 a, u64 b) {
    u64 d; asm("mul.rn.f32x2 %0,%1,%2;" : "=l"(d) : "l"(a), "l"(b)); return d;
}
__device__ __forceinline__ u64 add2(u64 a, u64 b) {
    u64 d; asm("add.rn.f32x2 %0,%1,%2;" : "=l"(d) : "l"(a), "l"(b)); return d;
}

// ===========================================================================
// Kernel 0a: x -> fp16
// ===========================================================================
__global__ __launch_bounds__(256) void convert_x(
    const float* __restrict__ src, __half* __restrict__ dst, int n4)
{
    int i = blockIdx.x * blockDim.x + threadIdx.x;
    if (i >= n4) return;
    float4 v = ((const float4*)src)[i];
    uint2 hp;
    unsigned short* hu = (unsigned short*)&hp;
    hu[0] = __half_as_ushort(__float2half_rn(v.x));
    hu[1] = __half_as_ushort(__float2half_rn(v.y));
    hu[2] = __half_as_ushort(__float2half_rn(v.z));
    hu[3] = __half_as_ushort(__float2half_rn(v.w));
    ((uint2*)dst)[i] = hp;
}

// Kernel 0b: W -> fp16, three mats in one launch
__global__ __launch_bounds__(256) void convert_w(
    const float* __restrict__ wq, const float* __restrict__ wk,
    const float* __restrict__ wv, int n4)
{
    int i = blockIdx.x * blockDim.x + threadIdx.x;
    if (i >= n4) return;
    const float* src = (blockIdx.y == 0) ? wq : ((blockIdx.y == 1) ? wk : wv);
    size_t off = (size_t)blockIdx.y * D_ * D_ / 4;
    float4 v = ((const float4*)src)[i];
    uint2 hp;
    unsigned short* hu = (unsigned short*)&hp;
    hu[0] = __half_as_ushort(__float2half_rn(v.x));
    hu[1] = __half_as_ushort(__float2half_rn(v.y));
    hu[2] = __half_as_ushort(__float2half_rn(v.z));
    hu[3] = __half_as_ushort(__float2half_rn(v.w));
    ((uint2*)(g_wf))[off + i] = hp;
}

// ===========================================================================
// Kernel 1: QKV projection, single fp16 mma.sync
// ===========================================================================
#define TILE_E   (128 * 40)
#define TILE_B   (TILE_E * 2)
#define GEMM_SMEM (2 * 2 * TILE_B)

__global__ __launch_bounds__(256, 2) void qkv_gemm_mma()
{
    extern __shared__ __align__(16) char smem[];
    __half* sb = (__half*)smem;
    const uint32_t sbase = smem_u32(smem);

    const int tid  = threadIdx.x;
    const int lane = tid & 31;
    const int wid  = tid >> 5;
    const int wm   = (wid >> 1) * 32;
    const int wn   = (wid & 1) * 64;
    const int n0   = blockIdx.x * 128;
    const int m0   = blockIdx.y * 128;
    const int mat  = blockIdx.z;

    const __half* A_g = g_xf + (size_t)m0 * D_;
    const __half* B_g = g_wf + (size_t)mat * D_ * D_ + (size_t)n0 * D_;
    __half* yf = (mat == 0) ? g_qf : ((mat == 1) ? g_kf : g_vf);

    const int lrow  = tid >> 1;
    const int lhalf = tid & 1;

    float acc[2][8][4];
#pragma unroll
    for (int i = 0; i < 2; i++)
#pragma unroll
        for (int j = 0; j < 8; j++)
#pragma unroll
            for (int c = 0; c < 4; c++) acc[i][j][c] = 0.0f;

    const int r  = lane >> 2;
    const int c2 = (lane & 3) * 2;

    auto load_tiles = [&](int buf, int k0) {
        const size_t go = (size_t)lrow * D_ + k0 + lhalf * 16;
        const uint32_t so = sbase + buf * 2 * TILE_B + lrow * 80 + lhalf * 32;
        cp16(so + 0 * TILE_B,      A_g + go);
        cp16(so + 0 * TILE_B + 16, A_g + go + 8);
        cp16(so + 1 * TILE_B,      B_g + go);
        cp16(so + 1 * TILE_B + 16, B_g + go + 8);
    };

    load_tiles(0, 0);
    CP_COMMIT();

    for (int it = 0; it < 32; it++) {
        const int cur = it & 1;
        if (it + 1 < 32) {
            load_tiles(cur ^ 1, (it + 1) * 32);
            CP_COMMIT();
            CP_WAIT(1);
        } else {
            CP_WAIT(0);
        }
        __syncthreads();

        const __half* Ah = sb + (cur * 2 + 0) * TILE_E;
        const __half* Bh = sb + (cur * 2 + 1) * TILE_E;

#pragma unroll
        for (int ks = 0; ks < 2; ks++) {
            const int kof = ks * 16;
            uint32_t ah[2][4];
#pragma unroll
            for (int mm = 0; mm < 2; mm++) {
                int row0 = wm + mm * 16 + r;
                const __half* p = Ah + row0 * 40 + kof + c2;
                ah[mm][0] = *(const uint32_t*)(p);
                ah[mm][1] = *(const uint32_t*)(p + 8 * 40);
                ah[mm][2] = *(const uint32_t*)(p + 8);
                ah[mm][3] = *(const uint32_t*)(p + 8 * 40 + 8);
            }
#pragma unroll
            for (int nn = 0; nn < 8; nn++) {
                int nrow = wn + nn * 8 + r;
                const __half* pb = Bh + nrow * 40 + kof + c2;
                uint32_t b0 = *(const uint32_t*)(pb);
                uint32_t b1 = *(const uint32_t*)(pb + 8);
#pragma unroll
                for (int mm = 0; mm < 2; mm++) {
                    float* d = acc[mm][nn];
                    mma_f16(d[0], d[1], d[2], d[3],
                            ah[mm][0], ah[mm][1], ah[mm][2], ah[mm][3], b0, b1);
                }
            }
        }
        __syncthreads();
    }

#pragma unroll
    for (int mm = 0; mm < 2; mm++) {
#pragma unroll
        for (int nn = 0; nn < 8; nn++) {
            int row = m0 + wm + mm * 16 + r;
            int col = n0 + wn + nn * 8 + c2;
            __half2 h01 = __floats2half2_rn(acc[mm][nn][0], acc[mm][nn][1]);
            *(uint32_t*)&yf[(size_t)row * D_ + col] = *(uint32_t*)&h01;
            __half2 h23 = __floats2half2_rn(acc[mm][nn][2], acc[mm][nn][3]);
            *(uint32_t*)&yf[(size_t)(row + 8) * D_ + col] = *(uint32_t*)&h23;
        }
    }
}

// ===========================================================================
// Kernel 2: palace attention — R11 exact: 256 thr, warps 4m x 2n (32x64
// warp tiles), deg-4 packed exp2 + IADD exponent, lsum via ones-column MMA.
// ===========================================================================
#define TB    18432
#define ROWB  144
#define ATTN_SMEM (5 * TB)

__global__ __launch_bounds__(256, 1) void palace_attn_tc(
    const float* __restrict__ wp, float* __restrict__ out)
{
    extern __shared__ __align__(128) char smem[];
    const uint32_t sb32 = smem_u32(smem);
    const int tid  = threadIdx.x;
    const int lane = tid & 31;
    const int wid  = tid >> 5;
    const int wm4  = wid >> 1;
    const int wn2  = wid & 1;
    const int r_   = lane >> 2;
    const int cq   = lane & 3;
    const int qt   = blockIdx.x;
    const int bh   = blockIdx.y;
    const int b    = bh >> 4;
    const int h    = bh & 15;

    const float sigw = 1.0f / (1.0f + expf(-wp[0]));
    const float cI = 0.125f * LOG2E;
    const float cX = cI * sigw;
    const u64 cI2 = pk2(cI, cI), cX2 = pk2(cX, cX);
    const u64 magic2  = pk2(12582912.0f, 12582912.0f);
    const u64 nmagic2 = pk2(-12582912.0f, -12582912.0f);
    const u64 neg1_2  = pk2(-1.0f, -1.0f);
    const u64 T4 = pk2(9.6181291e-3f, 9.6181291e-3f);
    const u64 T3 = pk2(5.5504109e-2f, 5.5504109e-2f);
    const u64 T2 = pk2(2.4022651e-1f, 2.4022651e-1f);
    const u64 T1 = pk2(6.9314718e-1f, 6.9314718e-1f);
    const u64 T0 = pk2(1.0f, 1.0f);
    const uint32_t ONESB = 0x3C003C00u;   // half2(1,1)

    const int lrow  = tid >> 1;
    const int lhalf = tid & 1;
    const size_t grow_base = ((size_t)b * T_) * D_ + (size_t)h * 64 + lhalf * 32;

    auto ld4 = [&](uint32_t soff, const __half* gp) {
#pragma unroll
        for (int kk = 0; kk < 4; kk++)
            cp16(sb32 + soff + lrow * ROWB + lhalf * 64 + kk * 16, gp + kk * 8);
    };
    {
        const size_t go = grow_base + (size_t)(qt * 128 + lrow) * D_;
        ld4(0, g_qf + go);
    }
    auto ldkv = [&](int buf, int kt) {
        const size_t go = grow_base + (size_t)(kt * 128 + lrow) * D_;
        const uint32_t off = TB + buf * 2 * TB;
        ld4(off,      g_kf + go);
        ld4(off + TB, g_vf + go);
    };
    ldkv(0, 0);
    CP_COMMIT();

    float o[2][8][4];
    float ls[2][4];                     // lsum accumulators (ones-MMA)
#pragma unroll
    for (int mm = 0; mm < 2; mm++) {
#pragma unroll
        for (int c = 0; c < 4; c++) ls[mm][c] = 0.f;
#pragma unroll
        for (int j = 0; j < 8; j++)
#pragma unroll
            for (int c = 0; c < 4; c++) o[mm][j][c] = 0.f;
    }

    const int arowb = wm4 * 32 + r_;
    const int krowb = wn2 * 64 + r_;
    const int vg = lane >> 3, vrr = lane & 7;
    const int vrow_off = wn2 * 64 + ((vg & 1) ? 8 : 0) + vrr;
    const int vcolB = ((vg >> 1) * 8) * 2;
    const int blk0base = (wm4 & 1) * 4;

    for (int kt = 0; kt < 16; kt++) {
        const int cur = kt & 1;
        if (kt + 1 < 16) { ldkv(cur ^ 1, kt + 1); CP_COMMIT(); CP_WAIT(1); }
        else             { CP_WAIT(0); }
        __syncthreads();

        const uint32_t KHo = TB + cur * 2 * TB;
        const uint32_t VHo = KHo + TB;

        // ---- S = Q K^T ----
        float s[2][8][4];
#pragma unroll
        for (int mm = 0; mm < 2; mm++)
#pragma unroll
            for (int j = 0; j < 8; j++)
#pragma unroll
                for (int c = 0; c < 4; c++) s[mm][j][c] = 0.f;

#pragma unroll
        for (int ks = 0; ks < 4; ks++) {
            const int cb = (ks * 16 + 2 * cq) * 2;
            uint32_t aq[2][4];
#pragma unroll
            for (int mm = 0; mm < 2; mm++) {
                const char* q0 = smem + (arowb + mm * 16) * ROWB + cb;
                aq[mm][0] = *(const uint32_t*)(q0);
                aq[mm][1] = *(const uint32_t*)(q0 + 8 * ROWB);
                aq[mm][2] = *(const uint32_t*)(q0 + 16);
                aq[mm][3] = *(const uint32_t*)(q0 + 8 * ROWB + 16);
            }
#pragma unroll
            for (int j = 0; j < 8; j++) {
                const char* kp = smem + KHo + (krowb + j * 8) * ROWB + cb;
                uint32_t b0 = *(const uint32_t*)(kp);
                uint32_t b1 = *(const uint32_t*)(kp + 16);
#pragma unroll
                for (int mm = 0; mm < 2; mm++) {
                    float* d = s[mm][j];
                    mma_f16(d[0], d[1], d[2], d[3],
                            aq[mm][0], aq[mm][1], aq[mm][2], aq[mm][3], b0, b1);
                }
            }
        }

        // ---- exp2 softmax (deg-4 poly, IADD exponent) + PV + lsum MMA ----
#pragma unroll
        for (int t = 0; t < 4; t++) {
            uint32_t ph[2][4];
#pragma unroll
            for (int jj = 0; jj < 2; jj++) {
                const int j = 2 * t + jj;
#pragma unroll
                for (int mm = 0; mm < 2; mm++) {
                    const int blk0 = blk0base + mm * 2;
#pragma unroll
                    for (int half = 0; half < 2; half++) {
                        const u64 mf2 = (j == blk0 + half) ? cI2 : cX2;
                        u64 s2 = pk2(s[mm][j][half * 2], s[mm][j][half * 2 + 1]);
                        u64 x2 = mul2(s2, mf2);
                        u64 t2 = add2(x2, magic2);
                        u64 n2 = add2(t2, nmagic2);
                        u64 f2 = fma2(n2, neg1_2, x2);
                        u64 p2 = fma2(T4, f2, T3);
                        p2 = fma2(p2, f2, T2);
                        p2 = fma2(p2, f2, T1);
                        p2 = fma2(p2, f2, T0);
                        // exponent folded in by integer add of n<<23
                        uint32_t tl = (uint32_t)t2, th = (uint32_t)(t2 >> 32);
                        float p0, p1; upk2(p2, p0, p1);
                        float pe0 = __uint_as_float(__float_as_uint(p0) + (tl << 23));
                        float pe1 = __uint_as_float(__float_as_uint(p1) + (th << 23));
                        __half2 h2 = __floats2half2_rn(pe0, pe1);
                        ph[mm][jj * 2 + half] = *(uint32_t*)&h2;
                    }
                }
            }
            const uint32_t va0 = sb32 + VHo + (vrow_off + t * 16) * ROWB + vcolB;
#pragma unroll
            for (int jnp = 0; jnp < 4; jnp++) {
                uint32_t v0, v1, v2, v3;
                ldsm4t(v0, v1, v2, v3, va0 + jnp * 32);
#pragma unroll
                for (int mm = 0; mm < 2; mm++) {
                    float* o0 = o[mm][jnp * 2];
                    mma_f16(o0[0], o0[1], o0[2], o0[3],
                            ph[mm][0], ph[mm][1], ph[mm][2], ph[mm][3], v0, v1);
                    float* o1 = o[mm][jnp * 2 + 1];
                    mma_f16(o1[0], o1[1], o1[2], o1[3],
                            ph[mm][0], ph[mm][1], ph[mm][2], ph[mm][3], v2, v3);
                }
            }
            // row-sum via ones-column MMA (l = P @ 1)
#pragma unroll
            for (int mm = 0; mm < 2; mm++) {
                mma_f16(ls[mm][0], ls[mm][1], ls[mm][2], ls[mm][3],
                        ph[mm][0], ph[mm][1], ph[mm][2], ph[mm][3], ONESB, ONESB);
            }
        }
        __syncthreads();
    }

    // ---- cross-warp combine (wn2 pair shares rows) ----
    float* Ost = (float*)(smem + TB);
    float* Lst = (float*)(smem + TB + 128 * 68 * 4);
    if (wn2 == 1) {
#pragma unroll
        for (int mm = 0; mm < 2; mm++) {
            int row = wm4 * 32 + mm * 16 + r_;
#pragma unroll
            for (int jn = 0; jn < 8; jn++) {
                int col = jn * 8 + 2 * cq;
                *(float2*)&Ost[row * 68 + col]       = make_float2(o[mm][jn][0], o[mm][jn][1]);
                *(float2*)&Ost[(row + 8) * 68 + col] = make_float2(o[mm][jn][2], o[mm][jn][3]);
            }
            if (cq == 0) {
                Lst[row]     = ls[mm][0];
                Lst[row + 8] = ls[mm][2];
            }
        }
    }
    __syncthreads();
    if (wn2 == 0) {
#pragma unroll
        for (int mm = 0; mm < 2; mm++) {
            int row = wm4 * 32 + mm * 16 + r_;
            float inv0 = 1.0f / (ls[mm][0] + Lst[row]);
            float inv1 = 1.0f / (ls[mm][2] + Lst[row + 8]);
            float* op0 = out + ((size_t)b * T_ + qt * 128 + row) * D_ + h * 64;
            float* op1 = op0 + 8 * D_;
#pragma unroll
            for (int jn = 0; jn < 8; jn++) {
                int col = jn * 8 + 2 * cq;
                float2 a0 = *(float2*)&Ost[row * 68 + col];
                float2 a1 = *(float2*)&Ost[(row + 8) * 68 + col];
                float2 w0 = make_float2((o[mm][jn][0] + a0.x) * inv0,
                                        (o[mm][jn][1] + a0.y) * inv0);
                float2 w1 = make_float2((o[mm][jn][2] + a1.x) * inv1,
                                        (o[mm][jn][3] + a1.y) * inv1);
                *(float2*)&op0[col] = w0;
                *(float2*)&op1[col] = w1;
            }
        }
    }
}

// ---------------------------------------------------------------------------
extern "C" void kernel_launch(void* const* d_in, const int* in_sizes, int n_in,
                              void* d_out, int out_size)
{
    const float* x  = (const float*)d_in[0];
    const float* Wq = (const float*)d_in[1];
    const float* Wk = (const float*)d_in[2];
    const float* Wv = (const float*)d_in[3];
    const float* wp = (const float*)d_in[4];
    float* out = (float*)d_out;

    __half* xf;
    cudaGetSymbolAddress((void**)&xf, g_xf);

    cudaFuncSetAttribute(qkv_gemm_mma, cudaFuncAttributeMaxDynamicSharedMemorySize,
                         GEMM_SMEM);
    cudaFuncSetAttribute(palace_attn_tc, cudaFuncAttributeMaxDynamicSharedMemorySize,
                         ATTN_SMEM);

    int n4x = BT_ * D_ / 4;
    convert_x<<<(n4x + 255) / 256, 256>>>(x, xf, n4x);
    int n4w = D_ * D_ / 4;
    convert_w<<<dim3((n4w + 255) / 256, 3), 256>>>(Wq, Wk, Wv, n4w);

    qkv_gemm_mma<<<dim3(8, 64, 3), 256, GEMM_SMEM>>>();
    palace_attn_tc<<<dim3(T_ / 128, B_ * H_), 256, ATTN_SMEM>>>(wp, out);
}

// round 16
// speedup vs baseline: 1.2685x; 1.2637x over previous
#include <cuda_runtime.h>
#include <cuda_fp16.h>
#include <cstdint>
#include <math.h>

#define B_  4
#define T_  2048
#define D_  1024
#define H_  16
#define BT_ (B_ * T_)
#define LOG2E 1.4426950408889634f

typedef unsigned long long u64;

// GEMM inputs: x fp16, W fp16
__device__ __half g_xf[(size_t)BT_ * D_];
__device__ __half g_wf[3ull * D_ * D_];
// Attention operands: fp16
__device__ __half g_qf[(size_t)BT_ * D_];
__device__ __half g_kf[(size_t)BT_ * D_];
__device__ __half g_vf[(size_t)BT_ * D_];

// ---- portable PTX helpers -------------------------------------------------
__device__ __forceinline__ uint32_t smem_u32(const void* p) {
    uint32_t a;
    asm("{ .reg .u64 t; cvta.to.shared.u64 t, %1; cvt.u32.u64 %0, t; }"
        : "=r"(a) : "l"(p));
    return a;
}
__device__ __forceinline__ void cp16(uint32_t s, const void* g) {
    asm volatile("cp.async.cg.shared.global [%0], [%1], 16;"
                 :: "r"(s), "l"(g) : "memory");
}
#define CP_COMMIT() asm volatile("cp.async.commit_group;" ::: "memory")
#define CP_WAIT(n)  asm volatile("cp.async.wait_group %0;" :: "n"(n) : "memory")

__device__ __forceinline__ void mma_f16(float& d0, float& d1, float& d2, float& d3,
                                        uint32_t a0, uint32_t a1, uint32_t a2, uint32_t a3,
                                        uint32_t b0, uint32_t b1) {
    asm volatile("mma.sync.aligned.m16n8k16.row.col.f32.f16.f16.f32 "
                 "{%0,%1,%2,%3},{%4,%5,%6,%7},{%8,%9},{%0,%1,%2,%3};"
                 : "+f"(d0), "+f"(d1), "+f"(d2), "+f"(d3)
                 : "r"(a0), "r"(a1), "r"(a2), "r"(a3), "r"(b0), "r"(b1));
}
__device__ __forceinline__ void ldsm4t(uint32_t& r0, uint32_t& r1,
                                       uint32_t& r2, uint32_t& r3, uint32_t a) {
    asm volatile("ldmatrix.sync.aligned.m8n8.x4.trans.shared.b16 {%0,%1,%2,%3}, [%4];"
                 : "=r"(r0), "=r"(r1), "=r"(r2), "=r"(r3) : "r"(a));
}
// ---- packed f32x2 ---------------------------------------------------------
__device__ __forceinline__ u64 pk2(float lo, float hi) {
    u64 r; asm("mov.b64 %0,{%1,%2};" : "=l"(r) : "f"(lo), "f"(hi)); return r;
}
__device__ __forceinline__ void upk2(u64 v, float& lo, float& hi) {
    asm("mov.b64 {%0,%1},%2;" : "=f"(lo), "=f"(hi) : "l"(v));
}
__device__ __forceinline__ u64 fma2(u64 a, u64 b, u64 c) {
    u64 d; asm("fma.rn.f32x2 %0,%1,%2,%3;" : "=l"(d) : "l"(a), "l"(b), "l"(c)); return d;
}
__device__ __forceinline__ u64 mul2(u64 a, u64 b) {
    u64 d; asm("mul.rn.f32x2 %0,%1,%2;" : "=l"(d) : "l"(a), "l"(b)); return d;
}
__device__ __forceinline__ u64 add2(u64 a, u64 b) {
    u64 d; asm("add.rn.f32x2 %0,%1,%2;" : "=l"(d) : "l"(a), "l"(b)); return d;
}

// ===========================================================================
// Kernel 0a: x -> fp16
// ===========================================================================
__global__ __launch_bounds__(256) void convert_x(
    const float* __restrict__ src, __half* __restrict__ dst, int n4)
{
    int i = blockIdx.x * blockDim.x + threadIdx.x;
    if (i >= n4) return;
    float4 v = ((const float4*)src)[i];
    uint2 hp;
    unsigned short* hu = (unsigned short*)&hp;
    hu[0] = __half_as_ushort(__float2half_rn(v.x));
    hu[1] = __half_as_ushort(__float2half_rn(v.y));
    hu[2] = __half_as_ushort(__float2half_rn(v.z));
    hu[3] = __half_as_ushort(__float2half_rn(v.w));
    ((uint2*)dst)[i] = hp;
}

// Kernel 0b: W -> fp16, three mats in one launch
__global__ __launch_bounds__(256) void convert_w(
    const float* __restrict__ wq, const float* __restrict__ wk,
    const float* __restrict__ wv, int n4)
{
    int i = blockIdx.x * blockDim.x + threadIdx.x;
    if (i >= n4) return;
    const float* src = (blockIdx.y == 0) ? wq : ((blockIdx.y == 1) ? wk : wv);
    size_t off = (size_t)blockIdx.y * D_ * D_ / 4;
    float4 v = ((const float4*)src)[i];
    uint2 hp;
    unsigned short* hu = (unsigned short*)&hp;
    hu[0] = __half_as_ushort(__float2half_rn(v.x));
    hu[1] = __half_as_ushort(__float2half_rn(v.y));
    hu[2] = __half_as_ushort(__float2half_rn(v.z));
    hu[3] = __half_as_ushort(__float2half_rn(v.w));
    ((uint2*)(g_wf))[off + i] = hp;
}

// ===========================================================================
// Kernel 1: QKV projection, single fp16 mma.sync (unchanged)
// ===========================================================================
#define TILE_E   (128 * 40)
#define TILE_B   (TILE_E * 2)
#define GEMM_SMEM (2 * 2 * TILE_B)

__global__ __launch_bounds__(256, 2) void qkv_gemm_mma()
{
    extern __shared__ __align__(16) char smem[];
    __half* sb = (__half*)smem;
    const uint32_t sbase = smem_u32(smem);

    const int tid  = threadIdx.x;
    const int lane = tid & 31;
    const int wid  = tid >> 5;
    const int wm   = (wid >> 1) * 32;
    const int wn   = (wid & 1) * 64;
    const int n0   = blockIdx.x * 128;
    const int m0   = blockIdx.y * 128;
    const int mat  = blockIdx.z;

    const __half* A_g = g_xf + (size_t)m0 * D_;
    const __half* B_g = g_wf + (size_t)mat * D_ * D_ + (size_t)n0 * D_;
    __half* yf = (mat == 0) ? g_qf : ((mat == 1) ? g_kf : g_vf);

    const int lrow  = tid >> 1;
    const int lhalf = tid & 1;

    float acc[2][8][4];
#pragma unroll
    for (int i = 0; i < 2; i++)
#pragma unroll
        for (int j = 0; j < 8; j++)
#pragma unroll
            for (int c = 0; c < 4; c++) acc[i][j][c] = 0.0f;

    const int r  = lane >> 2;
    const int c2 = (lane & 3) * 2;

    auto load_tiles = [&](int buf, int k0) {
        const size_t go = (size_t)lrow * D_ + k0 + lhalf * 16;
        const uint32_t so = sbase + buf * 2 * TILE_B + lrow * 80 + lhalf * 32;
        cp16(so + 0 * TILE_B,      A_g + go);
        cp16(so + 0 * TILE_B + 16, A_g + go + 8);
        cp16(so + 1 * TILE_B,      B_g + go);
        cp16(so + 1 * TILE_B + 16, B_g + go + 8);
    };

    load_tiles(0, 0);
    CP_COMMIT();

    for (int it = 0; it < 32; it++) {
        const int cur = it & 1;
        if (it + 1 < 32) {
            load_tiles(cur ^ 1, (it + 1) * 32);
            CP_COMMIT();
            CP_WAIT(1);
        } else {
            CP_WAIT(0);
        }
        __syncthreads();

        const __half* Ah = sb + (cur * 2 + 0) * TILE_E;
        const __half* Bh = sb + (cur * 2 + 1) * TILE_E;

#pragma unroll
        for (int ks = 0; ks < 2; ks++) {
            const int kof = ks * 16;
            uint32_t ah[2][4];
#pragma unroll
            for (int mm = 0; mm < 2; mm++) {
                int row0 = wm + mm * 16 + r;
                const __half* p = Ah + row0 * 40 + kof + c2;
                ah[mm][0] = *(const uint32_t*)(p);
                ah[mm][1] = *(const uint32_t*)(p + 8 * 40);
                ah[mm][2] = *(const uint32_t*)(p + 8);
                ah[mm][3] = *(const uint32_t*)(p + 8 * 40 + 8);
            }
#pragma unroll
            for (int nn = 0; nn < 8; nn++) {
                int nrow = wn + nn * 8 + r;
                const __half* pb = Bh + nrow * 40 + kof + c2;
                uint32_t b0 = *(const uint32_t*)(pb);
                uint32_t b1 = *(const uint32_t*)(pb + 8);
#pragma unroll
                for (int mm = 0; mm < 2; mm++) {
                    float* d = acc[mm][nn];
                    mma_f16(d[0], d[1], d[2], d[3],
                            ah[mm][0], ah[mm][1], ah[mm][2], ah[mm][3], b0, b1);
                }
            }
        }
        __syncthreads();
    }

#pragma unroll
    for (int mm = 0; mm < 2; mm++) {
#pragma unroll
        for (int nn = 0; nn < 8; nn++) {
            int row = m0 + wm + mm * 16 + r;
            int col = n0 + wn + nn * 8 + c2;
            __half2 h01 = __floats2half2_rn(acc[mm][nn][0], acc[mm][nn][1]);
            *(uint32_t*)&yf[(size_t)row * D_ + col] = *(uint32_t*)&h01;
            __half2 h23 = __floats2half2_rn(acc[mm][nn][2], acc[mm][nn][3]);
            *(uint32_t*)&yf[(size_t)(row + 8) * D_ + col] = *(uint32_t*)&h23;
        }
    }
}

// ===========================================================================
// Kernel 2: palace attention — R11 base with software-pipelined exp ahead of
// PV (double-buffered ph) and per-SMSP chunk-order stagger.
// ===========================================================================
#define TB    18432
#define ROWB  144
#define ATTN_SMEM (5 * TB)

__global__ __launch_bounds__(256, 1) void palace_attn_tc(
    const float* __restrict__ wp, float* __restrict__ out)
{
    extern __shared__ __align__(128) char smem[];
    const uint32_t sb32 = smem_u32(smem);
    const int tid  = threadIdx.x;
    const int lane = tid & 31;
    const int wid  = tid >> 5;
    const int wm4  = wid >> 1;
    const int wn2  = wid & 1;
    const int r_   = lane >> 2;
    const int cq   = lane & 3;
    const int qt   = blockIdx.x;
    const int bh   = blockIdx.y;
    const int b    = bh >> 4;
    const int h    = bh & 15;

    const float sigw = 1.0f / (1.0f + expf(-wp[0]));
    const float cI = 0.125f * LOG2E;
    const float cX = cI * sigw;
    const u64 cI2 = pk2(cI, cI), cX2 = pk2(cX, cX);
    const u64 magic2  = pk2(12582912.0f, 12582912.0f);
    const u64 nmagic2 = pk2(-12582912.0f, -12582912.0f);
    const u64 neg1_2  = pk2(-1.0f, -1.0f);
    const u64 T4 = pk2(9.6181291e-3f, 9.6181291e-3f);
    const u64 T3 = pk2(5.5504109e-2f, 5.5504109e-2f);
    const u64 T2 = pk2(2.4022651e-1f, 2.4022651e-1f);
    const u64 T1 = pk2(6.9314718e-1f, 6.9314718e-1f);
    const u64 T0 = pk2(1.0f, 1.0f);
    const uint32_t ONESB = 0x3C003C00u;

    const int lrow  = tid >> 1;
    const int lhalf = tid & 1;
    const size_t grow_base = ((size_t)b * T_) * D_ + (size_t)h * 64 + lhalf * 32;

    auto ld4 = [&](uint32_t soff, const __half* gp) {
#pragma unroll
        for (int kk = 0; kk < 4; kk++)
            cp16(sb32 + soff + lrow * ROWB + lhalf * 64 + kk * 16, gp + kk * 8);
    };
    {
        const size_t go = grow_base + (size_t)(qt * 128 + lrow) * D_;
        ld4(0, g_qf + go);
    }
    auto ldkv = [&](int buf, int kt) {
        const size_t go = grow_base + (size_t)(kt * 128 + lrow) * D_;
        const uint32_t off = TB + buf * 2 * TB;
        ld4(off,      g_kf + go);
        ld4(off + TB, g_vf + go);
    };
    ldkv(0, 0);
    CP_COMMIT();

    float o[2][8][4];
    float ls[2][4];
#pragma unroll
    for (int mm = 0; mm < 2; mm++) {
#pragma unroll
        for (int c = 0; c < 4; c++) ls[mm][c] = 0.f;
#pragma unroll
        for (int j = 0; j < 8; j++)
#pragma unroll
            for (int c = 0; c < 4; c++) o[mm][j][c] = 0.f;
    }

    const int arowb = wm4 * 32 + r_;
    const int krowb = wn2 * 64 + r_;
    const int vg = lane >> 3, vrr = lane & 7;
    const int vrow_off = wn2 * 64 + ((vg & 1) ? 8 : 0) + vrr;
    const int vcolB = ((vg >> 1) * 8) * 2;
    const int blk0base = (wm4 & 1) * 4;
    // stagger: warps co-resident on an SMSP (wid vs wid+4 -> wm4 0/2 or 1/3)
    // start their chunk sequence at different offsets
    const int tofs = ((wm4 >> 1) & 1) * 2;

    for (int kt = 0; kt < 16; kt++) {
        const int cur = kt & 1;
        if (kt + 1 < 16) { ldkv(cur ^ 1, kt + 1); CP_COMMIT(); CP_WAIT(1); }
        else             { CP_WAIT(0); }
        __syncthreads();

        const uint32_t KHo = TB + cur * 2 * TB;
        const uint32_t VHo = KHo + TB;

        // ---- S = Q K^T ----
        float s[2][8][4];
#pragma unroll
        for (int mm = 0; mm < 2; mm++)
#pragma unroll
            for (int j = 0; j < 8; j++)
#pragma unroll
                for (int c = 0; c < 4; c++) s[mm][j][c] = 0.f;

#pragma unroll
        for (int ks = 0; ks < 4; ks++) {
            const int cb = (ks * 16 + 2 * cq) * 2;
            uint32_t aq[2][4];
#pragma unroll
            for (int mm = 0; mm < 2; mm++) {
                const char* q0 = smem + (arowb + mm * 16) * ROWB + cb;
                aq[mm][0] = *(const uint32_t*)(q0);
                aq[mm][1] = *(const uint32_t*)(q0 + 8 * ROWB);
                aq[mm][2] = *(const uint32_t*)(q0 + 16);
                aq[mm][3] = *(const uint32_t*)(q0 + 8 * ROWB + 16);
            }
#pragma unroll
            for (int j = 0; j < 8; j++) {
                const char* kp = smem + KHo + (krowb + j * 8) * ROWB + cb;
                uint32_t b0 = *(const uint32_t*)(kp);
                uint32_t b1 = *(const uint32_t*)(kp + 16);
#pragma unroll
                for (int mm = 0; mm < 2; mm++) {
                    float* d = s[mm][j];
                    mma_f16(d[0], d[1], d[2], d[3],
                            aq[mm][0], aq[mm][1], aq[mm][2], aq[mm][3], b0, b1);
                }
            }
        }

        // ---- software-pipelined exp -> PV ----
        auto exp_chunk = [&](int t, uint32_t phx[2][4]) {
#pragma unroll
            for (int jj = 0; jj < 2; jj++) {
                const int j = 2 * t + jj;
#pragma unroll
                for (int mm = 0; mm < 2; mm++) {
                    const int blk0 = blk0base + mm * 2;
#pragma unroll
                    for (int half = 0; half < 2; half++) {
                        const u64 mf2 = (j == blk0 + half) ? cI2 : cX2;
                        u64 s2 = pk2(s[mm][j][half * 2], s[mm][j][half * 2 + 1]);
                        u64 x2 = mul2(s2, mf2);
                        u64 t2 = add2(x2, magic2);
                        u64 n2 = add2(t2, nmagic2);
                        u64 f2 = fma2(n2, neg1_2, x2);
                        u64 p2 = fma2(T4, f2, T3);
                        p2 = fma2(p2, f2, T2);
                        p2 = fma2(p2, f2, T1);
                        p2 = fma2(p2, f2, T0);
                        uint32_t tl = (uint32_t)t2, th = (uint32_t)(t2 >> 32);
                        float p0, p1; upk2(p2, p0, p1);
                        float pe0 = __uint_as_float(__float_as_uint(p0) + (tl << 23));
                        float pe1 = __uint_as_float(__float_as_uint(p1) + (th << 23));
                        __half2 h2 = __floats2half2_rn(pe0, pe1);
                        phx[mm][jj * 2 + half] = *(uint32_t*)&h2;
                    }
                }
            }
        };
        auto pv_chunk = [&](int t, uint32_t phx[2][4]) {
            const uint32_t va0 = sb32 + VHo + (vrow_off + t * 16) * ROWB + vcolB;
#pragma unroll
            for (int jnp = 0; jnp < 4; jnp++) {
                uint32_t v0, v1, v2, v3;
                ldsm4t(v0, v1, v2, v3, va0 + jnp * 32);
#pragma unroll
                for (int mm = 0; mm < 2; mm++) {
                    float* o0 = o[mm][jnp * 2];
                    mma_f16(o0[0], o0[1], o0[2], o0[3],
                            phx[mm][0], phx[mm][1], phx[mm][2], phx[mm][3], v0, v1);
                    float* o1 = o[mm][jnp * 2 + 1];
                    mma_f16(o1[0], o1[1], o1[2], o1[3],
                            phx[mm][0], phx[mm][1], phx[mm][2], phx[mm][3], v2, v3);
                }
            }
#pragma unroll
            for (int mm = 0; mm < 2; mm++) {
                mma_f16(ls[mm][0], ls[mm][1], ls[mm][2], ls[mm][3],
                        phx[mm][0], phx[mm][1], phx[mm][2], phx[mm][3], ONESB, ONESB);
            }
        };

        uint32_t phb[2][2][4];         // double-buffered P fragments
        exp_chunk(tofs, phb[0]);
#pragma unroll
        for (int i = 0; i < 4; i++) {
            const int tcur = (tofs + i) & 3;
            if (i < 3) exp_chunk((tofs + i + 1) & 3, phb[(i + 1) & 1]);
            pv_chunk(tcur, phb[i & 1]);
        }
        __syncthreads();
    }

    // ---- cross-warp combine (wn2 pair shares rows) ----
    float* Ost = (float*)(smem + TB);
    float* Lst = (float*)(smem + TB + 128 * 68 * 4);
    if (wn2 == 1) {
#pragma unroll
        for (int mm = 0; mm < 2; mm++) {
            int row = wm4 * 32 + mm * 16 + r_;
#pragma unroll
            for (int jn = 0; jn < 8; jn++) {
                int col = jn * 8 + 2 * cq;
                *(float2*)&Ost[row * 68 + col]       = make_float2(o[mm][jn][0], o[mm][jn][1]);
                *(float2*)&Ost[(row + 8) * 68 + col] = make_float2(o[mm][jn][2], o[mm][jn][3]);
            }
            if (cq == 0) {
                Lst[row]     = ls[mm][0];
                Lst[row + 8] = ls[mm][2];
            }
        }
    }
    __syncthreads();
    if (wn2 == 0) {
#pragma unroll
        for (int mm = 0; mm < 2; mm++) {
            int row = wm4 * 32 + mm * 16 + r_;
            float inv0 = 1.0f / (ls[mm][0] + Lst[row]);
            float inv1 = 1.0f / (ls[mm][2] + Lst[row + 8]);
            float* op0 = out + ((size_t)b * T_ + qt * 128 + row) * D_ + h * 64;
            float* op1 = op0 + 8 * D_;
#pragma unroll
            for (int jn = 0; jn < 8; jn++) {
                int col = jn * 8 + 2 * cq;
                float2 a0 = *(float2*)&Ost[row * 68 + col];
                float2 a1 = *(float2*)&Ost[(row + 8) * 68 + col];
                float2 w0 = make_float2((o[mm][jn][0] + a0.x) * inv0,
                                        (o[mm][jn][1] + a0.y) * inv0);
                float2 w1 = make_float2((o[mm][jn][2] + a1.x) * inv1,
                                        (o[mm][jn][3] + a1.y) * inv1);
                *(float2*)&op0[col] = w0;
                *(float2*)&op1[col] = w1;
            }
        }
    }
}

// ---------------------------------------------------------------------------
extern "C" void kernel_launch(void* const* d_in, const int* in_sizes, int n_in,
                              void* d_out, int out_size)
{
    const float* x  = (const float*)d_in[0];
    const float* Wq = (const float*)d_in[1];
    const float* Wk = (const float*)d_in[2];
    const float* Wv = (const float*)d_in[3];
    const float* wp = (const float*)d_in[4];
    float* out = (float*)d_out;

    __half* xf;
    cudaGetSymbolAddress((void**)&xf, g_xf);

    cudaFuncSetAttribute(qkv_gemm_mma, cudaFuncAttributeMaxDynamicSharedMemorySize,
                         GEMM_SMEM);
    cudaFuncSetAttribute(palace_attn_tc, cudaFuncAttributeMaxDynamicSharedMemorySize,
                         ATTN_SMEM);

    int n4x = BT_ * D_ / 4;
    convert_x<<<(n4x + 255) / 256, 256>>>(x, xf, n4x);
    int n4w = D_ * D_ / 4;
    convert_w<<<dim3((n4w + 255) / 256, 3), 256>>>(Wq, Wk, Wv, n4w);

    qkv_gemm_mma<<<dim3(8, 64, 3), 256, GEMM_SMEM>>>();
    palace_attn_tc<<<dim3(T_ / 128, B_ * H_), 256, ATTN_SMEM>>>(wp, out);
}

// round 17
// speedup vs baseline: 1.5472x; 1.2197x over previous
#include <cuda_runtime.h>
#include <cuda_fp16.h>
#include <cstdint>
#include <math.h>

#define B_  4
#define T_  2048
#define D_  1024
#define H_  16
#define BT_ (B_ * T_)
#define LOG2E 1.4426950408889634f

typedef unsigned long long u64;

// GEMM inputs: x fp16, W fp16
__device__ __half g_xf[(size_t)BT_ * D_];
__device__ __half g_wf[3ull * D_ * D_];
// Attention operands: fp16
__device__ __half g_qf[(size_t)BT_ * D_];
__device__ __half g_kf[(size_t)BT_ * D_];
__device__ __half g_vf[(size_t)BT_ * D_];

// ---- portable PTX helpers -------------------------------------------------
__device__ __forceinline__ uint32_t smem_u32(const void* p) {
    uint32_t a;
    asm("{ .reg .u64 t; cvta.to.shared.u64 t, %1; cvt.u32.u64 %0, t; }"
        : "=r"(a) : "l"(p));
    return a;
}
__device__ __forceinline__ void cp16(uint32_t s, const void* g) {
    asm volatile("cp.async.cg.shared.global [%0], [%1], 16;"
                 :: "r"(s), "l"(g) : "memory");
}
#define CP_COMMIT() asm volatile("cp.async.commit_group;" ::: "memory")
#define CP_WAIT(n)  asm volatile("cp.async.wait_group %0;" :: "n"(n) : "memory")

__device__ __forceinline__ void mma_f16(float& d0, float& d1, float& d2, float& d3,
                                        uint32_t a0, uint32_t a1, uint32_t a2, uint32_t a3,
                                        uint32_t b0, uint32_t b1) {
    asm volatile("mma.sync.aligned.m16n8k16.row.col.f32.f16.f16.f32 "
                 "{%0,%1,%2,%3},{%4,%5,%6,%7},{%8,%9},{%0,%1,%2,%3};"
                 : "+f"(d0), "+f"(d1), "+f"(d2), "+f"(d3)
                 : "r"(a0), "r"(a1), "r"(a2), "r"(a3), "r"(b0), "r"(b1));
}
__device__ __forceinline__ void ldsm4t(uint32_t& r0, uint32_t& r1,
                                       uint32_t& r2, uint32_t& r3, uint32_t a) {
    asm volatile("ldmatrix.sync.aligned.m8n8.x4.trans.shared.b16 {%0,%1,%2,%3}, [%4];"
                 : "=r"(r0), "=r"(r1), "=r"(r2), "=r"(r3) : "r"(a));
}
// ---- packed f32x2 ---------------------------------------------------------
__device__ __forceinline__ u64 pk2(float lo, float hi) {
    u64 r; asm("mov.b64 %0,{%1,%2};" : "=l"(r) : "f"(lo), "f"(hi)); return r;
}
__device__ __forceinline__ void upk2(u64 v, float& lo, float& hi) {
    asm("mov.b64 {%0,%1},%2;" : "=f"(lo), "=f"(hi) : "l"(v));
}
__device__ __forceinline__ u64 fma2(u64 a, u64 b, u64 c) {
    u64 d; asm("fma.rn.f32x2 %0,%1,%2,%3;" : "=l"(d) : "l"(a), "l"(b), "l"(c)); return d;
}
__device__ __forceinline__ u64 mul2(u64 a, u64 b) {
    u64 d; asm("mul.rn.f32x2 %0,%1,%2;" : "=l"(d) : "l"(a), "l"(b)); return d;
}
__device__ __forceinline__ u64 add2(u64 a, u64 b) {
    u64 d; asm("add.rn.f32x2 %0,%1,%2;" : "=l"(d) : "l"(a), "l"(b)); return d;
}

// ===========================================================================
// Kernel 0a: x -> fp16
// ===========================================================================
__global__ __launch_bounds__(256) void convert_x(
    const float* __restrict__ src, __half* __restrict__ dst, int n4)
{
    int i = blockIdx.x * blockDim.x + threadIdx.x;
    if (i >= n4) return;
    float4 v = ((const float4*)src)[i];
    uint2 hp;
    unsigned short* hu = (unsigned short*)&hp;
    hu[0] = __half_as_ushort(__float2half_rn(v.x));
    hu[1] = __half_as_ushort(__float2half_rn(v.y));
    hu[2] = __half_as_ushort(__float2half_rn(v.z));
    hu[3] = __half_as_ushort(__float2half_rn(v.w));
    ((uint2*)dst)[i] = hp;
}

// Kernel 0b: W -> fp16, three mats in one launch
__global__ __launch_bounds__(256) void convert_w(
    const float* __restrict__ wq, const float* __restrict__ wk,
    const float* __restrict__ wv, int n4)
{
    int i = blockIdx.x * blockDim.x + threadIdx.x;
    if (i >= n4) return;
    const float* src = (blockIdx.y == 0) ? wq : ((blockIdx.y == 1) ? wk : wv);
    size_t off = (size_t)blockIdx.y * D_ * D_ / 4;
    float4 v = ((const float4*)src)[i];
    uint2 hp;
    unsigned short* hu = (unsigned short*)&hp;
    hu[0] = __half_as_ushort(__float2half_rn(v.x));
    hu[1] = __half_as_ushort(__float2half_rn(v.y));
    hu[2] = __half_as_ushort(__float2half_rn(v.z));
    hu[3] = __half_as_ushort(__float2half_rn(v.w));
    ((uint2*)(g_wf))[off + i] = hp;
}

// ===========================================================================
// Kernel 1: QKV projection, single fp16 mma.sync (unchanged from R11)
// ===========================================================================
#define TILE_E   (128 * 40)
#define TILE_B   (TILE_E * 2)
#define GEMM_SMEM (2 * 2 * TILE_B)

__global__ __launch_bounds__(256, 2) void qkv_gemm_mma()
{
    extern __shared__ __align__(16) char smem[];
    __half* sb = (__half*)smem;
    const uint32_t sbase = smem_u32(smem);

    const int tid  = threadIdx.x;
    const int lane = tid & 31;
    const int wid  = tid >> 5;
    const int wm   = (wid >> 1) * 32;
    const int wn   = (wid & 1) * 64;
    const int n0   = blockIdx.x * 128;
    const int m0   = blockIdx.y * 128;
    const int mat  = blockIdx.z;

    const __half* A_g = g_xf + (size_t)m0 * D_;
    const __half* B_g = g_wf + (size_t)mat * D_ * D_ + (size_t)n0 * D_;
    __half* yf = (mat == 0) ? g_qf : ((mat == 1) ? g_kf : g_vf);

    const int lrow  = tid >> 1;
    const int lhalf = tid & 1;

    float acc[2][8][4];
#pragma unroll
    for (int i = 0; i < 2; i++)
#pragma unroll
        for (int j = 0; j < 8; j++)
#pragma unroll
            for (int c = 0; c < 4; c++) acc[i][j][c] = 0.0f;

    const int r  = lane >> 2;
    const int c2 = (lane & 3) * 2;

    auto load_tiles = [&](int buf, int k0) {
        const size_t go = (size_t)lrow * D_ + k0 + lhalf * 16;
        const uint32_t so = sbase + buf * 2 * TILE_B + lrow * 80 + lhalf * 32;
        cp16(so + 0 * TILE_B,      A_g + go);
        cp16(so + 0 * TILE_B + 16, A_g + go + 8);
        cp16(so + 1 * TILE_B,      B_g + go);
        cp16(so + 1 * TILE_B + 16, B_g + go + 8);
    };

    load_tiles(0, 0);
    CP_COMMIT();

    for (int it = 0; it < 32; it++) {
        const int cur = it & 1;
        if (it + 1 < 32) {
            load_tiles(cur ^ 1, (it + 1) * 32);
            CP_COMMIT();
            CP_WAIT(1);
        } else {
            CP_WAIT(0);
        }
        __syncthreads();

        const __half* Ah = sb + (cur * 2 + 0) * TILE_E;
        const __half* Bh = sb + (cur * 2 + 1) * TILE_E;

#pragma unroll
        for (int ks = 0; ks < 2; ks++) {
            const int kof = ks * 16;
            uint32_t ah[2][4];
#pragma unroll
            for (int mm = 0; mm < 2; mm++) {
                int row0 = wm + mm * 16 + r;
                const __half* p = Ah + row0 * 40 + kof + c2;
                ah[mm][0] = *(const uint32_t*)(p);
                ah[mm][1] = *(const uint32_t*)(p + 8 * 40);
                ah[mm][2] = *(const uint32_t*)(p + 8);
                ah[mm][3] = *(const uint32_t*)(p + 8 * 40 + 8);
            }
#pragma unroll
            for (int nn = 0; nn < 8; nn++) {
                int nrow = wn + nn * 8 + r;
                const __half* pb = Bh + nrow * 40 + kof + c2;
                uint32_t b0 = *(const uint32_t*)(pb);
                uint32_t b1 = *(const uint32_t*)(pb + 8);
#pragma unroll
                for (int mm = 0; mm < 2; mm++) {
                    float* d = acc[mm][nn];
                    mma_f16(d[0], d[1], d[2], d[3],
                            ah[mm][0], ah[mm][1], ah[mm][2], ah[mm][3], b0, b1);
                }
            }
        }
        __syncthreads();
    }

#pragma unroll
    for (int mm = 0; mm < 2; mm++) {
#pragma unroll
        for (int nn = 0; nn < 8; nn++) {
            int row = m0 + wm + mm * 16 + r;
            int col = n0 + wn + nn * 8 + c2;
            __half2 h01 = __floats2half2_rn(acc[mm][nn][0], acc[mm][nn][1]);
            *(uint32_t*)&yf[(size_t)row * D_ + col] = *(uint32_t*)&h01;
            __half2 h23 = __floats2half2_rn(acc[mm][nn][2], acc[mm][nn][3]);
            *(uint32_t*)&yf[(size_t)(row + 8) * D_ + col] = *(uint32_t*)&h23;
        }
    }
}

// ===========================================================================
// Kernel 2: palace attention — R11 base, restructured:
//  * Q fragments register-resident (loaded once; Q invariant across k-tiles)
//  * key chunks processed in pairs: 8 QK MMAs -> exp -> PV, fine-grain
//    overlap between pair jp's exp/PV and pair jp+1's QK MMAs (no barrier).
// Arithmetic order identical to R11 (rel_err canary: 5.441e-4).
// ===========================================================================
#define TB    18432
#define ROWB  144
#define ATTN_SMEM (5 * TB)

__global__ __launch_bounds__(256, 1) void palace_attn_tc(
    const float* __restrict__ wp, float* __restrict__ out)
{
    extern __shared__ __align__(128) char smem[];
    const uint32_t sb32 = smem_u32(smem);
    const int tid  = threadIdx.x;
    const int lane = tid & 31;
    const int wid  = tid >> 5;
    const int wm4  = wid >> 1;
    const int wn2  = wid & 1;
    const int r_   = lane >> 2;
    const int cq   = lane & 3;
    const int qt   = blockIdx.x;
    const int bh   = blockIdx.y;
    const int b    = bh >> 4;
    const int h    = bh & 15;

    const float sigw = 1.0f / (1.0f + expf(-wp[0]));
    const float cI = 0.125f * LOG2E;
    const float cX = cI * sigw;
    const u64 cI2 = pk2(cI, cI), cX2 = pk2(cX, cX);
    const u64 magic2  = pk2(12582912.0f, 12582912.0f);
    const u64 nmagic2 = pk2(-12582912.0f, -12582912.0f);
    const u64 neg1_2  = pk2(-1.0f, -1.0f);
    const u64 T4 = pk2(9.6181291e-3f, 9.6181291e-3f);
    const u64 T3 = pk2(5.5504109e-2f, 5.5504109e-2f);
    const u64 T2 = pk2(2.4022651e-1f, 2.4022651e-1f);
    const u64 T1 = pk2(6.9314718e-1f, 6.9314718e-1f);
    const u64 T0 = pk2(1.0f, 1.0f);
    const uint32_t ONESB = 0x3C003C00u;

    const int lrow  = tid >> 1;
    const int lhalf = tid & 1;
    const size_t grow_base = ((size_t)b * T_) * D_ + (size_t)h * 64 + lhalf * 32;

    auto ld4 = [&](uint32_t soff, const __half* gp) {
#pragma unroll
        for (int kk = 0; kk < 4; kk++)
            cp16(sb32 + soff + lrow * ROWB + lhalf * 64 + kk * 16, gp + kk * 8);
    };
    {
        const size_t go = grow_base + (size_t)(qt * 128 + lrow) * D_;
        ld4(0, g_qf + go);
    }
    auto ldkv = [&](int buf, int kt) {
        const size_t go = grow_base + (size_t)(kt * 128 + lrow) * D_;
        const uint32_t off = TB + buf * 2 * TB;
        ld4(off,      g_kf + go);
        ld4(off + TB, g_vf + go);
    };
    ldkv(0, 0);
    CP_COMMIT();

    float o[2][8][4];
    float ls[2][4];
#pragma unroll
    for (int mm = 0; mm < 2; mm++) {
#pragma unroll
        for (int c = 0; c < 4; c++) ls[mm][c] = 0.f;
#pragma unroll
        for (int j = 0; j < 8; j++)
#pragma unroll
            for (int c = 0; c < 4; c++) o[mm][j][c] = 0.f;
    }

    const int arowb = wm4 * 32 + r_;
    const int krowb = wn2 * 64 + r_;
    const int vg = lane >> 3, vrr = lane & 7;
    const int vrow_off = wn2 * 64 + ((vg & 1) ? 8 : 0) + vrr;
    const int vcolB = ((vg >> 1) * 8) * 2;
    const int blk0base = (wm4 & 1) * 4;

    uint32_t aqf[4][2][4];             // Q fragments, resident for whole kernel

    for (int kt = 0; kt < 16; kt++) {
        const int cur = kt & 1;
        if (kt + 1 < 16) { ldkv(cur ^ 1, kt + 1); CP_COMMIT(); CP_WAIT(1); }
        else             { CP_WAIT(0); }
        __syncthreads();

        if (kt == 0) {
            // Q tile now in smem; load all a-fragments once.
#pragma unroll
            for (int ks = 0; ks < 4; ks++) {
                const int cb = (ks * 16 + 2 * cq) * 2;
#pragma unroll
                for (int mm = 0; mm < 2; mm++) {
                    const char* q0 = smem + (arowb + mm * 16) * ROWB + cb;
                    aqf[ks][mm][0] = *(const uint32_t*)(q0);
                    aqf[ks][mm][1] = *(const uint32_t*)(q0 + 8 * ROWB);
                    aqf[ks][mm][2] = *(const uint32_t*)(q0 + 16);
                    aqf[ks][mm][3] = *(const uint32_t*)(q0 + 8 * ROWB + 16);
                }
            }
        }

        const uint32_t KHo = TB + cur * 2 * TB;
        const uint32_t VHo = KHo + TB;

        // ---- per key-chunk pair: QK MMAs -> exp -> PV ----
#pragma unroll
        for (int jp = 0; jp < 4; jp++) {
            float s[2][2][4];
#pragma unroll
            for (int mm = 0; mm < 2; mm++)
#pragma unroll
                for (int jj = 0; jj < 2; jj++)
#pragma unroll
                    for (int c = 0; c < 4; c++) s[mm][jj][c] = 0.f;

#pragma unroll
            for (int ks = 0; ks < 4; ks++) {
                const int cb = (ks * 16 + 2 * cq) * 2;
#pragma unroll
                for (int jj = 0; jj < 2; jj++) {
                    const int j = 2 * jp + jj;
                    const char* kp = smem + KHo + (krowb + j * 8) * ROWB + cb;
                    uint32_t b0 = *(const uint32_t*)(kp);
                    uint32_t b1 = *(const uint32_t*)(kp + 16);
#pragma unroll
                    for (int mm = 0; mm < 2; mm++) {
                        float* d = s[mm][jj];
                        mma_f16(d[0], d[1], d[2], d[3],
                                aqf[ks][mm][0], aqf[ks][mm][1],
                                aqf[ks][mm][2], aqf[ks][mm][3], b0, b1);
                    }
                }
            }

            // exp2 (deg-4 packed, IADD exponent)
            uint32_t ph[2][4];
#pragma unroll
            for (int jj = 0; jj < 2; jj++) {
                const int j = 2 * jp + jj;
#pragma unroll
                for (int mm = 0; mm < 2; mm++) {
                    const int blk0 = blk0base + mm * 2;
#pragma unroll
                    for (int half = 0; half < 2; half++) {
                        const u64 mf2 = (j == blk0 + half) ? cI2 : cX2;
                        u64 s2 = pk2(s[mm][jj][half * 2], s[mm][jj][half * 2 + 1]);
                        u64 x2 = mul2(s2, mf2);
                        u64 t2 = add2(x2, magic2);
                        u64 n2 = add2(t2, nmagic2);
                        u64 f2 = fma2(n2, neg1_2, x2);
                        u64 p2 = fma2(T4, f2, T3);
                        p2 = fma2(p2, f2, T2);
                        p2 = fma2(p2, f2, T1);
                        p2 = fma2(p2, f2, T0);
                        uint32_t tl = (uint32_t)t2, th = (uint32_t)(t2 >> 32);
                        float p0, p1; upk2(p2, p0, p1);
                        float pe0 = __uint_as_float(__float_as_uint(p0) + (tl << 23));
                        float pe1 = __uint_as_float(__float_as_uint(p1) + (th << 23));
                        __half2 h2 = __floats2half2_rn(pe0, pe1);
                        ph[mm][jj * 2 + half] = *(uint32_t*)&h2;
                    }
                }
            }

            // PV + lsum for this chunk
            const uint32_t va0 = sb32 + VHo + (vrow_off + jp * 16) * ROWB + vcolB;
#pragma unroll
            for (int jnp = 0; jnp < 4; jnp++) {
                uint32_t v0, v1, v2, v3;
                ldsm4t(v0, v1, v2, v3, va0 + jnp * 32);
#pragma unroll
                for (int mm = 0; mm < 2; mm++) {
                    float* o0 = o[mm][jnp * 2];
                    mma_f16(o0[0], o0[1], o0[2], o0[3],
                            ph[mm][0], ph[mm][1], ph[mm][2], ph[mm][3], v0, v1);
                    float* o1 = o[mm][jnp * 2 + 1];
                    mma_f16(o1[0], o1[1], o1[2], o1[3],
                            ph[mm][0], ph[mm][1], ph[mm][2], ph[mm][3], v2, v3);
                }
            }
#pragma unroll
            for (int mm = 0; mm < 2; mm++) {
                mma_f16(ls[mm][0], ls[mm][1], ls[mm][2], ls[mm][3],
                        ph[mm][0], ph[mm][1], ph[mm][2], ph[mm][3], ONESB, ONESB);
            }
        }
        __syncthreads();
    }

    // ---- cross-warp combine (wn2 pair shares rows) ----
    float* Ost = (float*)(smem + TB);
    float* Lst = (float*)(smem + TB + 128 * 68 * 4);
    if (wn2 == 1) {
#pragma unroll
        for (int mm = 0; mm < 2; mm++) {
            int row = wm4 * 32 + mm * 16 + r_;
#pragma unroll
            for (int jn = 0; jn < 8; jn++) {
                int col = jn * 8 + 2 * cq;
                *(float2*)&Ost[row * 68 + col]       = make_float2(o[mm][jn][0], o[mm][jn][1]);
                *(float2*)&Ost[(row + 8) * 68 + col] = make_float2(o[mm][jn][2], o[mm][jn][3]);
            }
            if (cq == 0) {
                Lst[row]     = ls[mm][0];
                Lst[row + 8] = ls[mm][2];
            }
        }
    }
    __syncthreads();
    if (wn2 == 0) {
#pragma unroll
        for (int mm = 0; mm < 2; mm++) {
            int row = wm4 * 32 + mm * 16 + r_;
            float inv0 = 1.0f / (ls[mm][0] + Lst[row]);
            float inv1 = 1.0f / (ls[mm][2] + Lst[row + 8]);
            float* op0 = out + ((size_t)b * T_ + qt * 128 + row) * D_ + h * 64;
            float* op1 = op0 + 8 * D_;
#pragma unroll
            for (int jn = 0; jn < 8; jn++) {
                int col = jn * 8 + 2 * cq;
                float2 a0 = *(float2*)&Ost[row * 68 + col];
                float2 a1 = *(float2*)&Ost[(row + 8) * 68 + col];
                float2 w0 = make_float2((o[mm][jn][0] + a0.x) * inv0,
                                        (o[mm][jn][1] + a0.y) * inv0);
                float2 w1 = make_float2((o[mm][jn][2] + a1.x) * inv1,
                                        (o[mm][jn][3] + a1.y) * inv1);
                *(float2*)&op0[col] = w0;
                *(float2*)&op1[col] = w1;
            }
        }
    }
}

// ---------------------------------------------------------------------------
extern "C" void kernel_launch(void* const* d_in, const int* in_sizes, int n_in,
                              void* d_out, int out_size)
{
    const float* x  = (const float*)d_in[0];
    const float* Wq = (const float*)d_in[1];
    const float* Wk = (const float*)d_in[2];
    const float* Wv = (const float*)d_in[3];
    const float* wp = (const float*)d_in[4];
    float* out = (float*)d_out;

    __half* xf;
    cudaGetSymbolAddress((void**)&xf, g_xf);

    cudaFuncSetAttribute(qkv_gemm_mma, cudaFuncAttributeMaxDynamicSharedMemorySize,
                         GEMM_SMEM);
    cudaFuncSetAttribute(palace_attn_tc, cudaFuncAttributeMaxDynamicSharedMemorySize,
                         ATTN_SMEM);

    int n4x = BT_ * D_ / 4;
    convert_x<<<(n4x + 255) / 256, 256>>>(x, xf, n4x);
    int n4w = D_ * D_ / 4;
    convert_w<<<dim3((n4w + 255) / 256, 3), 256>>>(Wq, Wk, Wv, n4w);

    qkv_gemm_mma<<<dim3(8, 64, 3), 256, GEMM_SMEM>>>();
    palace_attn_tc<<<dim3(T_ / 128, B_ * H_), 256, ATTN_SMEM>>>(wp, out);
}